// round 2
// baseline (speedup 1.0000x reference)
#include <cuda_runtime.h>
#include <math.h>

// ---------------------------------------------------------------------------
// MoEImage: B=32, CIN=HID=OUT=64, H=W=128, E=8 experts (top-2), S=2 shared.
// Phase A: features = gelu(x @ fe_w^T + fe_b)   -> d_feat [B,64,H,W]
// Phase B: gf[b][c] = mean_pixels(features)     -> d_gf   [32,64]
// Phase C: gating MLP + top-2 softmax(T=2)      -> d_dw   [32,8]
// Phase D: out = 0.5*(gelu(f@s0)+gelu(f@s1)) + w0*gelu(f@e_i0) + w1*gelu(f@e_i1)
// ---------------------------------------------------------------------------

#define NPIX   16384            // H*W
#define NPIX_B (64 * 16384)     // per-sample feature/out plane count

__device__ float d_feat[32 * 64 * 16384];  // 128 MiB scratch
__device__ float d_gf[32 * 64];
__device__ float d_dw[32 * 8];

__device__ __forceinline__ float gelu_f(float v) {
    return 0.5f * v * (1.0f + erff(v * 0.70710678118654752440f));
}

// ------------------------------ Phase A ------------------------------------
__global__ __launch_bounds__(256) void feat_kernel(
    const float* __restrict__ x, const float* __restrict__ fe_w,
    const float* __restrict__ fe_b)
{
    __shared__ __align__(16) float sw[64 * 64];
    __shared__ float sb[64];
    const int tid = threadIdx.x;
    for (int i = tid; i < 4096; i += 256) sw[i] = fe_w[i];
    if (tid < 64) sb[tid] = fe_b[tid];
    __syncthreads();

    const int b   = blockIdx.x >> 6;
    const int pix = ((blockIdx.x & 63) << 8) + tid;
    const float* xb = x + b * NPIX_B + pix;

    float f[64];
#pragma unroll
    for (int c = 0; c < 64; c++) f[c] = xb[c * NPIX];

    float* fb = d_feat + b * NPIX_B + pix;
#pragma unroll 1
    for (int o = 0; o < 64; o += 2) {
        float a0 = sb[o], a1 = sb[o + 1];
        const float4* w0 = (const float4*)(sw + o * 64);
        const float4* w1 = (const float4*)(sw + (o + 1) * 64);
#pragma unroll
        for (int g = 0; g < 16; g++) {
            float4 v0 = w0[g], v1 = w1[g];
            a0 = fmaf(f[4*g+0], v0.x, a0); a1 = fmaf(f[4*g+0], v1.x, a1);
            a0 = fmaf(f[4*g+1], v0.y, a0); a1 = fmaf(f[4*g+1], v1.y, a1);
            a0 = fmaf(f[4*g+2], v0.z, a0); a1 = fmaf(f[4*g+2], v1.z, a1);
            a0 = fmaf(f[4*g+3], v0.w, a0); a1 = fmaf(f[4*g+3], v1.w, a1);
        }
        fb[o * NPIX]       = gelu_f(a0);
        fb[(o + 1) * NPIX] = gelu_f(a1);
    }
}

// ------------------------------ Phase B ------------------------------------
__global__ __launch_bounds__(256) void gf_kernel()
{
    const int tid = threadIdx.x;
    const float* p = d_feat + (size_t)blockIdx.x * NPIX;
    float s = 0.f;
    for (int i = tid; i < NPIX; i += 256) s += p[i];
    __shared__ float red[256];
    red[tid] = s;
    __syncthreads();
    for (int st = 128; st > 0; st >>= 1) {
        if (tid < st) red[tid] += red[tid + st];
        __syncthreads();
    }
    if (tid == 0) d_gf[blockIdx.x] = red[0] * (1.0f / 16384.0f);
}

// ------------------------------ Phase C ------------------------------------
__global__ __launch_bounds__(256) void gate_kernel(
    const float* __restrict__ g1_w, const float* __restrict__ g1_b,
    const float* __restrict__ bn1_g, const float* __restrict__ bn1_b,
    const float* __restrict__ ca1_w, const float* __restrict__ ca1_b,
    const float* __restrict__ ca2_w, const float* __restrict__ ca2_b,
    const float* __restrict__ g2_w, const float* __restrict__ g2_b,
    const float* __restrict__ bn2_g, const float* __restrict__ bn2_b,
    const float* __restrict__ g3_w, const float* __restrict__ g3_b)
{
    __shared__ float sgf[32 * 64];
    __shared__ float sh1[32 * 128];
    __shared__ float sm[32 * 8];
    __shared__ float shh[32 * 64];
    __shared__ float ssc[32 * 8];
    const int tid = threadIdx.x;
    const float rs = rsqrtf(1.0f + 1e-5f);

    for (int i = tid; i < 2048; i += 256) sgf[i] = d_gf[i];
    __syncthreads();

    // h1 = gelu(bn1(gf @ g1_w^T + g1_b))  [32,128]
    for (int i = tid; i < 32 * 128; i += 256) {
        int b = i >> 7, j = i & 127;
        float a = g1_b[j];
        const float* gr = sgf + b * 64;
        const float* wr = g1_w + j * 64;
#pragma unroll 8
        for (int c = 0; c < 64; c++) a = fmaf(gr[c], wr[c], a);
        a = a * (bn1_g[j] * rs) + bn1_b[j];
        sh1[i] = gelu_f(a);
    }
    __syncthreads();

    // mid = gelu(h1 @ ca1_w^T + ca1_b)  [32,8]
    if (tid < 256) {
        int b = tid >> 3, k = tid & 7;
        float a = ca1_b[k];
        const float* hr = sh1 + b * 128;
        const float* wr = ca1_w + k * 128;
#pragma unroll 8
        for (int j = 0; j < 128; j++) a = fmaf(hr[j], wr[j], a);
        sm[tid] = gelu_f(a);
    }
    __syncthreads();

    // h1 *= sigmoid(2 * (mid @ ca2_w^T + ca2_b))
    for (int i = tid; i < 32 * 128; i += 256) {
        int b = i >> 7, j = i & 127;
        float a = ca2_b[j];
        const float* mr = sm + b * 8;
        const float* wr = ca2_w + j * 8;
#pragma unroll
        for (int k = 0; k < 8; k++) a = fmaf(mr[k], wr[k], a);
        sh1[i] *= 1.0f / (1.0f + expf(-2.0f * a));
    }
    __syncthreads();

    // hh = gelu(bn2(h1 @ g2_w^T + g2_b))  [32,64]
    for (int i = tid; i < 32 * 64; i += 256) {
        int b = i >> 6, o = i & 63;
        float a = g2_b[o];
        const float* hr = sh1 + b * 128;
        const float* wr = g2_w + o * 128;
#pragma unroll 8
        for (int j = 0; j < 128; j++) a = fmaf(hr[j], wr[j], a);
        a = a * (bn2_g[o] * rs) + bn2_b[o];
        shh[i] = gelu_f(a);
    }
    __syncthreads();

    // scores = hh @ g3_w^T + g3_b  [32,8]
    if (tid < 256) {
        int b = tid >> 3, e = tid & 7;
        float a = g3_b[e];
        const float* hr = shh + b * 64;
        const float* wr = g3_w + e * 64;
#pragma unroll 8
        for (int c = 0; c < 64; c++) a = fmaf(hr[c], wr[c], a);
        ssc[tid] = a;
    }
    __syncthreads();

    // top-2 + softmax(T=2) -> dense weights
    if (tid < 32) {
        const float* sc = ssc + tid * 8;
        int i1 = 0; float v1 = sc[0];
#pragma unroll
        for (int e = 1; e < 8; e++) if (sc[e] > v1) { v1 = sc[e]; i1 = e; }
        int i2 = -1; float v2 = -3.4e38f;
#pragma unroll
        for (int e = 0; e < 8; e++) if (e != i1 && sc[e] > v2) { v2 = sc[e]; i2 = e; }
        float w1 = 1.0f / (1.0f + expf((v2 - v1) * 0.5f));
        float* dw = d_dw + tid * 8;
#pragma unroll
        for (int e = 0; e < 8; e++) dw[e] = 0.0f;
        dw[i1] = w1;
        dw[i2] = 1.0f - w1;
    }
}

// ------------------------------ Phase D ------------------------------------
__global__ __launch_bounds__(256) void out_kernel(
    const float* __restrict__ s_w, const float* __restrict__ s_b,
    const float* __restrict__ e_w, const float* __restrict__ e_b,
    float* __restrict__ out)
{
    extern __shared__ __align__(16) float Wm[];  // 4 * 4096 floats = 64 KB
    __shared__ float Bv[4 * 64];
    __shared__ float cw2, cw3;
    __shared__ int sel0, sel1;

    const int tid = threadIdx.x;
    const int b   = blockIdx.x >> 6;

    if (tid == 0) {
        int s0 = -1, s1 = -1; float w0 = 0.f, w1 = 0.f;
        const float* dw = d_dw + b * 8;
#pragma unroll
        for (int e = 0; e < 8; e++) {
            float v = dw[e];
            if (v != 0.0f) { if (s0 < 0) { s0 = e; w0 = v; } else { s1 = e; w1 = v; } }
        }
        sel0 = s0; sel1 = s1; cw2 = w0; cw3 = w1;
    }
    __syncthreads();
    const int e0 = sel0, e1 = sel1;

    for (int i = tid; i < 4096; i += 256) {
        Wm[i]            = s_w[i];
        Wm[4096 + i]     = s_w[4096 + i];
        Wm[2 * 4096 + i] = e_w[e0 * 4096 + i];
        Wm[3 * 4096 + i] = e_w[e1 * 4096 + i];
    }
    if (tid < 64) {
        Bv[tid]       = s_b[tid];
        Bv[64 + tid]  = s_b[64 + tid];
        Bv[128 + tid] = e_b[e0 * 64 + tid];
        Bv[192 + tid] = e_b[e1 * 64 + tid];
    }
    __syncthreads();

    const int pix = ((blockIdx.x & 63) << 8) + tid;
    const float* fb = d_feat + b * NPIX_B + pix;
    float f[64];
#pragma unroll
    for (int c = 0; c < 64; c++) f[c] = fb[c * NPIX];

    const float wr2 = cw2, wr3 = cw3;
    float* ob = out + b * NPIX_B + pix;

#pragma unroll 1
    for (int o = 0; o < 64; o++) {
        float a0 = Bv[o], a1 = Bv[64 + o], a2 = Bv[128 + o], a3 = Bv[192 + o];
        const float4* w0 = (const float4*)(Wm + o * 64);
        const float4* w1 = (const float4*)(Wm + 4096 + o * 64);
        const float4* w2 = (const float4*)(Wm + 2 * 4096 + o * 64);
        const float4* w3 = (const float4*)(Wm + 3 * 4096 + o * 64);
#pragma unroll
        for (int g = 0; g < 16; g++) {
            float4 v0 = w0[g], v1 = w1[g], v2 = w2[g], v3 = w3[g];
            float x0 = f[4*g+0], x1 = f[4*g+1], x2 = f[4*g+2], x3 = f[4*g+3];
            a0 = fmaf(x0, v0.x, a0); a1 = fmaf(x0, v1.x, a1);
            a2 = fmaf(x0, v2.x, a2); a3 = fmaf(x0, v3.x, a3);
            a0 = fmaf(x1, v0.y, a0); a1 = fmaf(x1, v1.y, a1);
            a2 = fmaf(x1, v2.y, a2); a3 = fmaf(x1, v3.y, a3);
            a0 = fmaf(x2, v0.z, a0); a1 = fmaf(x2, v1.z, a1);
            a2 = fmaf(x2, v2.z, a2); a3 = fmaf(x2, v3.z, a3);
            a0 = fmaf(x3, v0.w, a0); a1 = fmaf(x3, v1.w, a1);
            a2 = fmaf(x3, v2.w, a2); a3 = fmaf(x3, v3.w, a3);
        }
        ob[o * NPIX] = 0.5f * (gelu_f(a0) + gelu_f(a1))
                     + wr2 * gelu_f(a2) + wr3 * gelu_f(a3);
    }
}

// ---------------------------------------------------------------------------
extern "C" void kernel_launch(void* const* d_in, const int* in_sizes, int n_in,
                              void* d_out, int out_size)
{
    const float* x     = (const float*)d_in[0];
    const float* fe_w  = (const float*)d_in[1];
    const float* fe_b  = (const float*)d_in[2];
    const float* s_w   = (const float*)d_in[3];
    const float* s_b   = (const float*)d_in[4];
    const float* e_w   = (const float*)d_in[5];
    const float* e_b   = (const float*)d_in[6];
    const float* g1_w  = (const float*)d_in[7];
    const float* g1_b  = (const float*)d_in[8];
    const float* bn1_g = (const float*)d_in[9];
    const float* bn1_b = (const float*)d_in[10];
    const float* ca1_w = (const float*)d_in[11];
    const float* ca1_b = (const float*)d_in[12];
    const float* ca2_w = (const float*)d_in[13];
    const float* ca2_b = (const float*)d_in[14];
    const float* g2_w  = (const float*)d_in[15];
    const float* g2_b  = (const float*)d_in[16];
    const float* bn2_g = (const float*)d_in[17];
    const float* bn2_b = (const float*)d_in[18];
    const float* g3_w  = (const float*)d_in[19];
    const float* g3_b  = (const float*)d_in[20];
    float* out = (float*)d_out;

    static bool attr_done = false;
    if (!attr_done) {
        cudaFuncSetAttribute(out_kernel,
                             cudaFuncAttributeMaxDynamicSharedMemorySize,
                             4 * 4096 * sizeof(float));
        attr_done = true;
    }

    feat_kernel<<<2048, 256>>>(x, fe_w, fe_b);
    gf_kernel<<<2048, 256>>>();
    gate_kernel<<<1, 256>>>(g1_w, g1_b, bn1_g, bn1_b, ca1_w, ca1_b,
                            ca2_w, ca2_b, g2_w, g2_b, bn2_g, bn2_b,
                            g3_w, g3_b);
    out_kernel<<<2048, 256, 4 * 4096 * sizeof(float)>>>(s_w, s_b, e_w, e_b, out);
}

// round 5
// speedup vs baseline: 1.2103x; 1.2103x over previous
#include <cuda_runtime.h>
#include <math.h>

// ---------------------------------------------------------------------------
// MoEImage: B=32, CIN=HID=OUT=64, H=W=128, E=8 experts (top-2), S=2 shared.
// wtrans : pre-transpose 11 64x64 weight matrices to [k][o] layout (d_wT)
// feat   : features = gelu(x @ fe_w^T + b), register-tiled; fused gf partials
// gate   : sum gf partials -> gating MLP -> top-2 softmax -> d_dw
// out    : register-tiled 4-matrix GEMM + gelu + weighted combine
// ---------------------------------------------------------------------------

#define NPIX   16384
#define NPIX_B (64 * 16384)

__device__ float d_feat[32 * 64 * 16384];   // [b][c][pix], 128 MiB
__device__ float d_gf_part[4096 * 64];      // per-feat-block channel partial sums
__device__ float d_dw[32 * 8];
__device__ float d_wT[11 * 4096];           // 0: fe, 1-2: shared, 3-10: experts

__device__ __forceinline__ float gelu_f(float v) {
    return 0.5f * v * (1.0f + erff(v * 0.70710678118654752440f));
}

// --------------------------- weight transpose ------------------------------
__global__ __launch_bounds__(256) void wtrans_kernel(
    const float* __restrict__ fe_w, const float* __restrict__ s_w,
    const float* __restrict__ e_w)
{
    const int m = blockIdx.x;   // 0..10
    const float* src = (m == 0) ? fe_w
                     : (m <= 2) ? s_w + (m - 1) * 4096
                                : e_w + (m - 3) * 4096;
    float* dst = d_wT + m * 4096;
    for (int i = threadIdx.x; i < 4096; i += 256) {
        int o = i >> 6, k = i & 63;
        dst[k * 64 + o] = src[i];
    }
}

// ------------------------------ Phase A ------------------------------------
// grid = 32 b * 128 tiles of 128 pixels; block 256 = 8 o_t * 32 p_t
// thread tile: 4 pix * 8 outputs
__global__ void __launch_bounds__(256, 3) feat_kernel(
    const float* __restrict__ x, const float* __restrict__ fe_b)
{
    extern __shared__ __align__(16) float smem[];
    float* sx = smem;          // [64 c][128 pix]  32 KB
    float* sw = smem + 8192;   // [64 k][64 o]     16 KB
    __shared__ float sb[64];

    const int tid  = threadIdx.x;
    const int b    = blockIdx.x >> 7;
    const int pix0 = (blockIdx.x & 127) << 7;

    for (int i = tid; i < 4096; i += 256) sw[i] = d_wT[i];
    if (tid < 64) sb[tid] = fe_b[tid];
    {
        const float* xb = x + (size_t)b * NPIX_B + pix0;
        int c = tid >> 5, j4 = (tid & 31) << 2;
#pragma unroll
        for (int r = 0; r < 8; r++, c += 8)
            *(float4*)&sx[c * 128 + j4] = *(const float4*)&xb[c * NPIX + j4];
    }
    __syncthreads();

    const int o_t = tid >> 5;   // 0..7  (warp id)
    const int p_t = tid & 31;   // 0..31 (lane)

    float acc[8][4];
#pragma unroll
    for (int oo = 0; oo < 8; oo++) {
        float bb = sb[o_t * 8 + oo];
#pragma unroll
        for (int p = 0; p < 4; p++) acc[oo][p] = bb;
    }

#pragma unroll 4
    for (int k = 0; k < 64; k++) {
        float4 f4 = *(float4*)&sx[k * 128 + p_t * 4];
        float4 w0 = *(float4*)&sw[k * 64 + o_t * 8];
        float4 w1 = *(float4*)&sw[k * 64 + o_t * 8 + 4];
        float fv[4] = {f4.x, f4.y, f4.z, f4.w};
        float wv[8] = {w0.x, w0.y, w0.z, w0.w, w1.x, w1.y, w1.z, w1.w};
#pragma unroll
        for (int oo = 0; oo < 8; oo++)
#pragma unroll
            for (int p = 0; p < 4; p++)
                acc[oo][p] = fmaf(fv[p], wv[oo], acc[oo][p]);
    }

    // epilogue: gelu + store [c][pix] + per-block channel partial sums
    float* fb = d_feat + (size_t)b * NPIX_B + pix0 + p_t * 4;
    float psum[8];
#pragma unroll
    for (int oo = 0; oo < 8; oo++) {
        float4 r;
        r.x = gelu_f(acc[oo][0]); r.y = gelu_f(acc[oo][1]);
        r.z = gelu_f(acc[oo][2]); r.w = gelu_f(acc[oo][3]);
        *(float4*)&fb[(o_t * 8 + oo) * NPIX] = r;
        psum[oo] = (r.x + r.y) + (r.z + r.w);
    }
#pragma unroll
    for (int oo = 0; oo < 8; oo++)
#pragma unroll
        for (int s = 16; s > 0; s >>= 1)
            psum[oo] += __shfl_xor_sync(0xffffffffu, psum[oo], s);
    if (p_t == 0) {
#pragma unroll
        for (int oo = 0; oo < 8; oo++)
            d_gf_part[blockIdx.x * 64 + o_t * 8 + oo] = psum[oo];
    }
}

// ------------------------------ Phase C ------------------------------------
__global__ __launch_bounds__(256) void gate_kernel(
    const float* __restrict__ g1_w, const float* __restrict__ g1_b,
    const float* __restrict__ bn1_g, const float* __restrict__ bn1_b,
    const float* __restrict__ ca1_w, const float* __restrict__ ca1_b,
    const float* __restrict__ ca2_w, const float* __restrict__ ca2_b,
    const float* __restrict__ g2_w, const float* __restrict__ g2_b,
    const float* __restrict__ bn2_g, const float* __restrict__ bn2_b,
    const float* __restrict__ g3_w, const float* __restrict__ g3_b)
{
    __shared__ float sgf[32 * 64];
    __shared__ float sh1[32 * 128];
    __shared__ float sm[32 * 8];
    __shared__ float shh[32 * 64];
    __shared__ float ssc[32 * 8];
    const int tid = threadIdx.x;
    const float rs = rsqrtf(1.0f + 1e-5f);

    // reduce per-block partials -> gf (deterministic fixed order)
    for (int i = tid; i < 2048; i += 256) {
        int bb = i >> 6, c = i & 63;
        const float* pp = d_gf_part + bb * (128 * 64) + c;
        float s = 0.f;
        for (int j = 0; j < 128; j++) s += pp[j * 64];
        sgf[i] = s * (1.0f / 16384.0f);
    }
    __syncthreads();

    // h1 = gelu(bn1(gf @ g1_w^T + g1_b))
    for (int i = tid; i < 32 * 128; i += 256) {
        int b = i >> 7, j = i & 127;
        float a = g1_b[j];
        const float* gr = sgf + b * 64;
        const float* wr = g1_w + j * 64;
#pragma unroll 8
        for (int c = 0; c < 64; c++) a = fmaf(gr[c], wr[c], a);
        a = a * (bn1_g[j] * rs) + bn1_b[j];
        sh1[i] = gelu_f(a);
    }
    __syncthreads();

    // mid = gelu(h1 @ ca1_w^T + ca1_b)
    {
        int b = tid >> 3, k = tid & 7;
        float a = ca1_b[k];
        const float* hr = sh1 + b * 128;
        const float* wr = ca1_w + k * 128;
#pragma unroll 8
        for (int j = 0; j < 128; j++) a = fmaf(hr[j], wr[j], a);
        sm[tid] = gelu_f(a);
    }
    __syncthreads();

    // h1 *= sigmoid(2 * (mid @ ca2_w^T + ca2_b))
    for (int i = tid; i < 32 * 128; i += 256) {
        int b = i >> 7, j = i & 127;
        float a = ca2_b[j];
        const float* mr = sm + b * 8;
        const float* wr = ca2_w + j * 8;
#pragma unroll
        for (int k = 0; k < 8; k++) a = fmaf(mr[k], wr[k], a);
        sh1[i] *= 1.0f / (1.0f + expf(-2.0f * a));
    }
    __syncthreads();

    // hh = gelu(bn2(h1 @ g2_w^T + g2_b))
    for (int i = tid; i < 32 * 64; i += 256) {
        int b = i >> 6, o = i & 63;
        float a = g2_b[o];
        const float* hr = sh1 + b * 128;
        const float* wr = g2_w + o * 128;
#pragma unroll 8
        for (int j = 0; j < 128; j++) a = fmaf(hr[j], wr[j], a);
        a = a * (bn2_g[o] * rs) + bn2_b[o];
        shh[i] = gelu_f(a);
    }
    __syncthreads();

    // scores = hh @ g3_w^T + g3_b
    {
        int b = tid >> 3, e = tid & 7;
        float a = g3_b[e];
        const float* hr = shh + b * 64;
        const float* wr = g3_w + e * 64;
#pragma unroll 8
        for (int c = 0; c < 64; c++) a = fmaf(hr[c], wr[c], a);
        ssc[tid] = a;
    }
    __syncthreads();

    if (tid < 32) {
        const float* sc = ssc + tid * 8;
        int i1 = 0; float v1 = sc[0];
#pragma unroll
        for (int e = 1; e < 8; e++) if (sc[e] > v1) { v1 = sc[e]; i1 = e; }
        int i2 = -1; float v2 = -3.4e38f;
#pragma unroll
        for (int e = 0; e < 8; e++) if (e != i1 && sc[e] > v2) { v2 = sc[e]; i2 = e; }
        float w1 = 1.0f / (1.0f + expf((v2 - v1) * 0.5f));
        float* dw = d_dw + tid * 8;
#pragma unroll
        for (int e = 0; e < 8; e++) dw[e] = 0.0f;
        dw[i1] = w1;
        dw[i2] = 1.0f - w1;
    }
}

// ------------------------------ Phase D ------------------------------------
// grid = 32 b * 256 tiles of 64 pixels; block 256 = 16 o_t * 16 p_t
// thread tile: 4 pix * 4 outputs * 4 matrices (s0, s1, e0, e1)
__global__ void __launch_bounds__(256, 2) out_kernel(
    const float* __restrict__ s_b, const float* __restrict__ e_b,
    float* __restrict__ out)
{
    extern __shared__ __align__(16) float smem[];
    float* sf = smem;          // [64 k][64 pix]        16 KB
    float* sw = smem + 4096;   // [4 mat][64 k][64 o]   64 KB
    __shared__ float Bv[256];
    __shared__ float cw2, cw3;
    __shared__ int sel0, sel1;

    const int tid  = threadIdx.x;
    const int b    = blockIdx.x >> 8;
    const int pix0 = (blockIdx.x & 255) << 6;

    if (tid == 0) {
        int s0 = -1, s1 = -1; float w0 = 0.f, w1 = 0.f;
        const float* dw = d_dw + b * 8;
#pragma unroll
        for (int e = 0; e < 8; e++) {
            float v = dw[e];
            if (v != 0.0f) { if (s0 < 0) { s0 = e; w0 = v; } else { s1 = e; w1 = v; } }
        }
        sel0 = s0; sel1 = s1; cw2 = w0; cw3 = w1;
    }
    __syncthreads();
    const int e0 = sel0, e1 = sel1;

    // stage 4 pre-transposed weight matrices ([k][o] layout, conflict-free)
    {
        const float* w0 = d_wT + 1 * 4096;
        const float* w1 = d_wT + 2 * 4096;
        const float* w2 = d_wT + (3 + e0) * 4096;
        const float* w3 = d_wT + (3 + e1) * 4096;
        for (int i = tid * 4; i < 4096; i += 1024) {
            *(float4*)&sw[i]            = *(const float4*)&w0[i];
            *(float4*)&sw[4096 + i]     = *(const float4*)&w1[i];
            *(float4*)&sw[2 * 4096 + i] = *(const float4*)&w2[i];
            *(float4*)&sw[3 * 4096 + i] = *(const float4*)&w3[i];
        }
    }
    if (tid < 64) {
        Bv[tid]       = s_b[tid];
        Bv[64 + tid]  = s_b[64 + tid];
        Bv[128 + tid] = e_b[e0 * 64 + tid];
        Bv[192 + tid] = e_b[e1 * 64 + tid];
    }
    // stage feature tile [k][64 pix]
    {
        const float* fbase = d_feat + (size_t)b * NPIX_B + pix0;
        int k = tid >> 4, j4 = (tid & 15) << 2;
#pragma unroll
        for (int r = 0; r < 4; r++, k += 16)
            *(float4*)&sf[k * 64 + j4] = *(const float4*)&fbase[k * NPIX + j4];
    }
    __syncthreads();

    const int o_t = tid >> 4;   // 0..15
    const int p_t = tid & 15;   // 0..15

    float acc[4][4][4];         // [mat][oo][pix]
#pragma unroll
    for (int m = 0; m < 4; m++)
#pragma unroll
        for (int oo = 0; oo < 4; oo++) {
            float bb = Bv[m * 64 + o_t * 4 + oo];
#pragma unroll
            for (int p = 0; p < 4; p++) acc[m][oo][p] = bb;
        }

#pragma unroll 2
    for (int k = 0; k < 64; k++) {
        float4 f4 = *(float4*)&sf[k * 64 + p_t * 4];
        float fv[4] = {f4.x, f4.y, f4.z, f4.w};
#pragma unroll
        for (int m = 0; m < 4; m++) {
            float4 w = *(float4*)&sw[m * 4096 + k * 64 + o_t * 4];
            float wv[4] = {w.x, w.y, w.z, w.w};
#pragma unroll
            for (int oo = 0; oo < 4; oo++)
#pragma unroll
                for (int p = 0; p < 4; p++)
                    acc[m][oo][p] = fmaf(fv[p], wv[oo], acc[m][oo][p]);
        }
    }

    const float wr2 = cw2, wr3 = cw3;
    float* ob = out + (size_t)b * NPIX_B + pix0 + p_t * 4;
#pragma unroll
    for (int oo = 0; oo < 4; oo++) {
        float r[4];
#pragma unroll
        for (int p = 0; p < 4; p++)
            r[p] = 0.5f * (gelu_f(acc[0][oo][p]) + gelu_f(acc[1][oo][p]))
                 + wr2 * gelu_f(acc[2][oo][p]) + wr3 * gelu_f(acc[3][oo][p]);
        float4 rv = {r[0], r[1], r[2], r[3]};
        *(float4*)&ob[(o_t * 4 + oo) * NPIX] = rv;
    }
}

// ---------------------------------------------------------------------------
extern "C" void kernel_launch(void* const* d_in, const int* in_sizes, int n_in,
                              void* d_out, int out_size)
{
    const float* x     = (const float*)d_in[0];
    const float* fe_w  = (const float*)d_in[1];
    const float* fe_b  = (const float*)d_in[2];
    const float* s_w   = (const float*)d_in[3];
    const float* s_b   = (const float*)d_in[4];
    const float* e_w   = (const float*)d_in[5];
    const float* e_b   = (const float*)d_in[6];
    const float* g1_w  = (const float*)d_in[7];
    const float* g1_b  = (const float*)d_in[8];
    const float* bn1_g = (const float*)d_in[9];
    const float* bn1_b = (const float*)d_in[10];
    const float* ca1_w = (const float*)d_in[11];
    const float* ca1_b = (const float*)d_in[12];
    const float* ca2_w = (const float*)d_in[13];
    const float* ca2_b = (const float*)d_in[14];
    const float* g2_w  = (const float*)d_in[15];
    const float* g2_b  = (const float*)d_in[16];
    const float* bn2_g = (const float*)d_in[17];
    const float* bn2_b = (const float*)d_in[18];
    const float* g3_w  = (const float*)d_in[19];
    const float* g3_b  = (const float*)d_in[20];
    float* out = (float*)d_out;

    static bool attr_done = false;
    if (!attr_done) {
        cudaFuncSetAttribute(feat_kernel,
                             cudaFuncAttributeMaxDynamicSharedMemorySize,
                             12288 * sizeof(float));
        cudaFuncSetAttribute(out_kernel,
                             cudaFuncAttributeMaxDynamicSharedMemorySize,
                             20480 * sizeof(float));
        attr_done = true;
    }

    wtrans_kernel<<<11, 256>>>(fe_w, s_w, e_w);
    feat_kernel<<<4096, 256, 12288 * sizeof(float)>>>(x, fe_b);
    gate_kernel<<<1, 256>>>(g1_w, g1_b, bn1_g, bn1_b, ca1_w, ca1_b,
                            ca2_w, ca2_b, g2_w, g2_b, bn2_g, bn2_b,
                            g3_w, g3_b);
    out_kernel<<<8192, 256, 20480 * sizeof(float)>>>(s_b, e_b, out);
}

// round 9
// speedup vs baseline: 1.6670x; 1.3773x over previous
#include <cuda_runtime.h>
#include <math.h>
#include <stdint.h>

// ---------------------------------------------------------------------------
// MoEImage via tf32 mma.sync tensor cores.
//   wquant : round all 11 64x64 weight matrices to tf32 (native [o][k] layout)
//   feat   : F = gelu(x@W^T+b) with m=pix tiles; x transposed in-register;
//            d_feat stored [b][pix][c]; fused gf partial sums
//   gate   : reduce gf partials -> gating MLP -> top-2 softmax -> d_dw
//   out    : 4-matrix tf32 GEMM (m=o, n=pix), gelu+coef in regs, smem combine
// ---------------------------------------------------------------------------

#define NPIX   16384
#define NPIX_B (64 * 16384)

__device__ float d_feat[32 * 64 * 16384];   // [b][pix][c]
__device__ float d_gf_part[4096 * 64];
__device__ float d_dw[32 * 8];
__device__ float d_wq[11 * 4096];           // tf32-rounded; 0: fe, 1-2: shared, 3-10: experts

__device__ __forceinline__ float gelu_f(float v) {
    return 0.5f * v * (1.0f + erff(v * 0.70710678118654752440f));
}
__device__ __forceinline__ float tf32r(float v) {
    uint32_t u;
    asm("cvt.rna.tf32.f32 %0, %1;" : "=r"(u) : "f"(v));
    return __uint_as_float(u);
}
// rows of 64 floats (16 segs of 16B); XOR-swizzled float offset of seg start
__device__ __forceinline__ int swz(int row, int seg) {
    return (row << 6) + ((seg ^ ((row ^ (row >> 3)) & 7)) << 2);
}
__device__ __forceinline__ void ldsm4(uint32_t a, uint32_t& r0, uint32_t& r1,
                                      uint32_t& r2, uint32_t& r3) {
    asm volatile("ldmatrix.sync.aligned.m8n8.x4.shared.b16 {%0,%1,%2,%3}, [%4];"
                 : "=r"(r0), "=r"(r1), "=r"(r2), "=r"(r3) : "r"(a));
}
__device__ __forceinline__ void mma8(float& c0, float& c1, float& c2, float& c3,
                                     uint32_t a0, uint32_t a1, uint32_t a2, uint32_t a3,
                                     uint32_t b0, uint32_t b1) {
    asm volatile("mma.sync.aligned.m16n8k8.row.col.f32.tf32.tf32.f32 "
                 "{%0,%1,%2,%3},{%4,%5,%6,%7},{%8,%9},{%0,%1,%2,%3};"
                 : "+f"(c0), "+f"(c1), "+f"(c2), "+f"(c3)
                 : "r"(a0), "r"(a1), "r"(a2), "r"(a3), "r"(b0), "r"(b1));
}

// --------------------------- weight quantize -------------------------------
__global__ __launch_bounds__(256) void wquant_kernel(
    const float* __restrict__ fe_w, const float* __restrict__ s_w,
    const float* __restrict__ e_w)
{
    const int m = blockIdx.x;   // 0..10
    const float* src = (m == 0) ? fe_w
                     : (m <= 2) ? s_w + (m - 1) * 4096
                                : e_w + (m - 3) * 4096;
    float* dst = d_wq + m * 4096;
    for (int i = threadIdx.x; i < 4096; i += 256) dst[i] = tf32r(src[i]);
}

// ------------------------------ Phase A ------------------------------------
// grid = 32 b * 128 tiles of 128 pix; block 256 = 8 warps.
// GEMM: m = pix (128, 8 strips of 16), n = o (64, 8 tiles), k = c (64).
// A = x^T [pix][c] (built in-register), B = fe_w [o][c] (native).
__global__ void __launch_bounds__(256) feat_kernel(
    const float* __restrict__ x, const float* __restrict__ fe_b)
{
    extern __shared__ __align__(16) float sm_[];
    float* sxT = sm_;           // [128 pix][64 c] swz  (8192 floats)
    float* swt = sm_ + 8192;    // [64 o][64 c]  swz  (4096 floats)
    float* sc  = sm_;           // staging [128 pix][64 o] swz (reuse)
    __shared__ float sb[64];
    __shared__ float red[512];

    const int tid = threadIdx.x, w = tid >> 5, l = tid & 31;
    const int b = blockIdx.x >> 7, pix0 = (blockIdx.x & 127) << 7;

    // stage fe weights (pre-rounded)
    for (int k = 0; k < 4; k++) {
        int i4 = tid + k * 256;
        float4 v = *(const float4*)(d_wq + i4 * 4);
        *(float4*)(swt + swz(i4 >> 4, i4 & 15)) = v;
    }
    if (tid < 64) sb[tid] = fe_b[tid];

    // stage x transposed (in-register 4x4 transpose) + tf32 round
    {
        const float* xb = x + (size_t)b * NPIX_B + pix0;
        for (int cc = 0; cc < 2; cc++) {
            int cq = w + cc * 8;   // c-quad 0..15
            float4 v[4];
#pragma unroll
            for (int j = 0; j < 4; j++)
                v[j] = *(const float4*)(xb + (size_t)(4 * cq + j) * NPIX + 4 * l);
#pragma unroll
            for (int p = 0; p < 4; p++) {
                float4 t;
                t.x = tf32r(((const float*)&v[0])[p]);
                t.y = tf32r(((const float*)&v[1])[p]);
                t.z = tf32r(((const float*)&v[2])[p]);
                t.w = tf32r(((const float*)&v[3])[p]);
                *(float4*)(sxT + swz(4 * l + p, cq)) = t;
            }
        }
    }
    __syncthreads();

    const uint32_t sxT_sh = (uint32_t)__cvta_generic_to_shared(sxT);
    const uint32_t swt_sh = (uint32_t)__cvta_generic_to_shared(swt);

    float acc[8][4];
    {
        int c0 = 2 * (l & 3);
#pragma unroll
        for (int nt = 0; nt < 8; nt++) {
            float b0v = sb[nt * 8 + c0], b1v = sb[nt * 8 + c0 + 1];
            acc[nt][0] = b0v; acc[nt][1] = b1v;
            acc[nt][2] = b0v; acc[nt][3] = b1v;
        }
    }

    const int tq = l >> 3, r8 = l & 7;
#pragma unroll
    for (int kk = 0; kk < 8; kk++) {
        uint32_t a0, a1, a2, a3;
        {
            int row = 16 * w + (tq & 1) * 8 + r8;
            int seg = 2 * kk + (tq >> 1);
            ldsm4(sxT_sh + 4 * swz(row, seg), a0, a1, a2, a3);
        }
        uint32_t bf[8][2];
#pragma unroll
        for (int g = 0; g < 4; g++) {
            int row = g * 16 + (tq >> 1) * 8 + r8;
            int seg = 2 * kk + (tq & 1);
            uint32_t r0, r1, r2, r3;
            ldsm4(swt_sh + 4 * swz(row, seg), r0, r1, r2, r3);
            bf[2 * g][0] = r0; bf[2 * g][1] = r1;
            bf[2 * g + 1][0] = r2; bf[2 * g + 1][1] = r3;
        }
#pragma unroll
        for (int nt = 0; nt < 8; nt++)
            mma8(acc[nt][0], acc[nt][1], acc[nt][2], acc[nt][3],
                 a0, a1, a2, a3, bf[nt][0], bf[nt][1]);
    }

    // gelu + tf32 round (features feed the next tf32 GEMM)
#pragma unroll
    for (int nt = 0; nt < 8; nt++)
#pragma unroll
        for (int i = 0; i < 4; i++) acc[nt][i] = tf32r(gelu_f(acc[nt][i]));

    __syncthreads();   // sxT/swt dead -> reuse as sc
    {
        int pr = 16 * w + (l >> 2);
        int c0 = 2 * (l & 3);
#pragma unroll
        for (int nt = 0; nt < 8; nt++) {
            int o = nt * 8 + c0;
            *(float2*)(sc + swz(pr, o >> 2) + (o & 3)) =
                make_float2(acc[nt][0], acc[nt][1]);
            *(float2*)(sc + swz(pr + 8, o >> 2) + (o & 3)) =
                make_float2(acc[nt][2], acc[nt][3]);
        }
    }
    __syncthreads();

    // copy-out [pix][c] + per-channel partial sums
    float4 ps = make_float4(0.f, 0.f, 0.f, 0.f);
    float* fb = d_feat + ((size_t)b * NPIX + pix0) * 64;
#pragma unroll
    for (int r = 0; r < 8; r++) {
        int idx = r * 256 + tid;
        int pix = idx >> 4, c4 = idx & 15;
        float4 v = *(float4*)(sc + swz(pix, c4));
        *(float4*)(fb + pix * 64 + c4 * 4) = v;
        ps.x += v.x; ps.y += v.y; ps.z += v.z; ps.w += v.w;
    }
    ps.x += __shfl_xor_sync(0xffffffffu, ps.x, 16);
    ps.y += __shfl_xor_sync(0xffffffffu, ps.y, 16);
    ps.z += __shfl_xor_sync(0xffffffffu, ps.z, 16);
    ps.w += __shfl_xor_sync(0xffffffffu, ps.w, 16);
    if (l < 16) *(float4*)(red + w * 64 + (tid & 15) * 4) = ps;
    __syncthreads();
    if (tid < 64) {
        float s = 0.f;
#pragma unroll
        for (int ww = 0; ww < 8; ww++) s += red[ww * 64 + tid];
        d_gf_part[blockIdx.x * 64 + tid] = s;
    }
}

// ------------------------------ Phase C ------------------------------------
__global__ __launch_bounds__(256) void gate_kernel(
    const float* __restrict__ g1_w, const float* __restrict__ g1_b,
    const float* __restrict__ bn1_g, const float* __restrict__ bn1_b,
    const float* __restrict__ ca1_w, const float* __restrict__ ca1_b,
    const float* __restrict__ ca2_w, const float* __restrict__ ca2_b,
    const float* __restrict__ g2_w, const float* __restrict__ g2_b,
    const float* __restrict__ bn2_g, const float* __restrict__ bn2_b,
    const float* __restrict__ g3_w, const float* __restrict__ g3_b)
{
    __shared__ float sgf[32 * 64];
    __shared__ float sh1[32 * 128];
    __shared__ float sm[32 * 8];
    __shared__ float shh[32 * 64];
    __shared__ float ssc[32 * 8];
    const int tid = threadIdx.x;
    const float rs = rsqrtf(1.0f + 1e-5f);

    for (int i = tid; i < 2048; i += 256) {
        int bb = i >> 6, c = i & 63;
        const float* pp = d_gf_part + bb * (128 * 64) + c;
        float s = 0.f;
        for (int j = 0; j < 128; j++) s += pp[j * 64];
        sgf[i] = s * (1.0f / 16384.0f);
    }
    __syncthreads();

    for (int i = tid; i < 32 * 128; i += 256) {
        int b = i >> 7, j = i & 127;
        float a = g1_b[j];
        const float* gr = sgf + b * 64;
        const float* wr = g1_w + j * 64;
#pragma unroll 8
        for (int c = 0; c < 64; c++) a = fmaf(gr[c], wr[c], a);
        a = a * (bn1_g[j] * rs) + bn1_b[j];
        sh1[i] = gelu_f(a);
    }
    __syncthreads();

    {
        int b = tid >> 3, k = tid & 7;
        float a = ca1_b[k];
        const float* hr = sh1 + b * 128;
        const float* wr = ca1_w + k * 128;
#pragma unroll 8
        for (int j = 0; j < 128; j++) a = fmaf(hr[j], wr[j], a);
        sm[tid] = gelu_f(a);
    }
    __syncthreads();

    for (int i = tid; i < 32 * 128; i += 256) {
        int b = i >> 7, j = i & 127;
        float a = ca2_b[j];
        const float* mr = sm + b * 8;
        const float* wr = ca2_w + j * 8;
#pragma unroll
        for (int k = 0; k < 8; k++) a = fmaf(mr[k], wr[k], a);
        sh1[i] *= 1.0f / (1.0f + expf(-2.0f * a));
    }
    __syncthreads();

    for (int i = tid; i < 32 * 64; i += 256) {
        int b = i >> 6, o = i & 63;
        float a = g2_b[o];
        const float* hr = sh1 + b * 128;
        const float* wr = g2_w + o * 128;
#pragma unroll 8
        for (int j = 0; j < 128; j++) a = fmaf(hr[j], wr[j], a);
        a = a * (bn2_g[o] * rs) + bn2_b[o];
        shh[i] = gelu_f(a);
    }
    __syncthreads();

    {
        int b = tid >> 3, e = tid & 7;
        float a = g3_b[e];
        const float* hr = shh + b * 64;
        const float* wr = g3_w + e * 64;
#pragma unroll 8
        for (int c = 0; c < 64; c++) a = fmaf(hr[c], wr[c], a);
        ssc[tid] = a;
    }
    __syncthreads();

    if (tid < 32) {
        const float* sc = ssc + tid * 8;
        int i1 = 0; float v1 = sc[0];
#pragma unroll
        for (int e = 1; e < 8; e++) if (sc[e] > v1) { v1 = sc[e]; i1 = e; }
        int i2 = -1; float v2 = -3.4e38f;
#pragma unroll
        for (int e = 0; e < 8; e++) if (e != i1 && sc[e] > v2) { v2 = sc[e]; i2 = e; }
        float w1 = 1.0f / (1.0f + expf((v2 - v1) * 0.5f));
        float* dw = d_dw + tid * 8;
#pragma unroll
        for (int e = 0; e < 8; e++) dw[e] = 0.0f;
        dw[i1] = w1;
        dw[i2] = 1.0f - w1;
    }
}

// ------------------------------ Phase D ------------------------------------
// grid = 32 b * 256 tiles of 64 pix; block 256 = 8 warps = (4 mats x 2 o-halves)
// GEMM per mat: m = o (64), n = pix (64), k = 64. A = weights [o][k],
// B = features [pix][k] (both ldmatrix-native). Combine through smem.
__global__ void __launch_bounds__(256, 2) out_kernel(
    const float* __restrict__ s_b, const float* __restrict__ e_b,
    float* __restrict__ out)
{
    extern __shared__ __align__(16) float sm_[];
    float* sfB = sm_;           // [64 pix][64 k] swz (4096)
    float* sw  = sm_ + 4096;    // [4 mat][64 o][64 k] swz (16384); reused for combine
    __shared__ float Bv[256];
    __shared__ float cws[4];
    __shared__ int msel[4];

    const int tid = threadIdx.x, w = tid >> 5, l = tid & 31;
    const int b = blockIdx.x >> 8, pix0 = (blockIdx.x & 255) << 6;

    if (tid == 0) {
        int s0 = -1, s1 = -1; float w0 = 0.f, w1 = 0.f;
        const float* dw = d_dw + b * 8;
#pragma unroll
        for (int e = 0; e < 8; e++) {
            float v = dw[e];
            if (v != 0.0f) { if (s0 < 0) { s0 = e; w0 = v; } else { s1 = e; w1 = v; } }
        }
        msel[0] = 1; msel[1] = 2; msel[2] = 3 + s0; msel[3] = 3 + s1;
        cws[0] = 0.5f; cws[1] = 0.5f; cws[2] = w0; cws[3] = w1;
    }
    __syncthreads();

    // stage 4 weight matrices (swizzled)
#pragma unroll
    for (int m = 0; m < 4; m++) {
        const float* src = d_wq + msel[m] * 4096;
#pragma unroll
        for (int k = 0; k < 4; k++) {
            int i4 = tid + k * 256;
            float4 v = *(const float4*)(src + i4 * 4);
            *(float4*)(sw + m * 4096 + swz(i4 >> 4, i4 & 15)) = v;
        }
    }
    // stage feature tile [pix][k] (contiguous in d_feat)
    {
        const float* fb = d_feat + ((size_t)b * NPIX + pix0) * 64;
#pragma unroll
        for (int k = 0; k < 4; k++) {
            int i4 = tid + k * 256;
            float4 v = *(const float4*)(fb + i4 * 4);
            *(float4*)(sfB + swz(i4 >> 4, i4 & 15)) = v;
        }
    }
    if (tid < 64) {
        Bv[tid]       = s_b[tid];
        Bv[64 + tid]  = s_b[64 + tid];
        Bv[128 + tid] = e_b[(msel[2] - 3) * 64 + tid];
        Bv[192 + tid] = e_b[(msel[3] - 3) * 64 + tid];
    }
    __syncthreads();

    const int mat = w >> 1, h = w & 1;
    const uint32_t sw_sh = (uint32_t)__cvta_generic_to_shared(sw + mat * 4096);
    const uint32_t sf_sh = (uint32_t)__cvta_generic_to_shared(sfB);

    float acc[2][8][4];
#pragma unroll
    for (int mt = 0; mt < 2; mt++) {
        int ro = 32 * h + 16 * mt + (l >> 2);
        float b0v = Bv[mat * 64 + ro], b1v = Bv[mat * 64 + ro + 8];
#pragma unroll
        for (int nt = 0; nt < 8; nt++) {
            acc[mt][nt][0] = b0v; acc[mt][nt][1] = b0v;
            acc[mt][nt][2] = b1v; acc[mt][nt][3] = b1v;
        }
    }

    const int tq = l >> 3, r8 = l & 7;
#pragma unroll
    for (int kk = 0; kk < 8; kk++) {
        uint32_t A[2][4];
#pragma unroll
        for (int mt = 0; mt < 2; mt++) {
            int row = 32 * h + 16 * mt + (tq & 1) * 8 + r8;
            int seg = 2 * kk + (tq >> 1);
            ldsm4(sw_sh + 4 * swz(row, seg), A[mt][0], A[mt][1], A[mt][2], A[mt][3]);
        }
        uint32_t Bf[8][2];
#pragma unroll
        for (int g = 0; g < 4; g++) {
            int row = g * 16 + (tq >> 1) * 8 + r8;
            int seg = 2 * kk + (tq & 1);
            uint32_t r0, r1, r2, r3;
            ldsm4(sf_sh + 4 * swz(row, seg), r0, r1, r2, r3);
            Bf[2 * g][0] = r0; Bf[2 * g][1] = r1;
            Bf[2 * g + 1][0] = r2; Bf[2 * g + 1][1] = r3;
        }
#pragma unroll
        for (int mt = 0; mt < 2; mt++)
#pragma unroll
            for (int nt = 0; nt < 8; nt++)
                mma8(acc[mt][nt][0], acc[mt][nt][1], acc[mt][nt][2], acc[mt][nt][3],
                     A[mt][0], A[mt][1], A[mt][2], A[mt][3],
                     Bf[nt][0], Bf[nt][1]);
    }

    const float coef = cws[mat];
    __syncthreads();   // weights dead -> reuse sw as 4 partial buffers [mat][o][pix]
    {
        int c0p = 2 * (l & 3);
#pragma unroll
        for (int mt = 0; mt < 2; mt++) {
            int ro = 32 * h + 16 * mt + (l >> 2);
#pragma unroll
            for (int nt = 0; nt < 8; nt++) {
                int pix = nt * 8 + c0p;
                float v0 = coef * gelu_f(acc[mt][nt][0]);
                float v1 = coef * gelu_f(acc[mt][nt][1]);
                float v2 = coef * gelu_f(acc[mt][nt][2]);
                float v3 = coef * gelu_f(acc[mt][nt][3]);
                *(float2*)(sw + mat * 4096 + swz(ro, pix >> 2) + (pix & 3)) =
                    make_float2(v0, v1);
                *(float2*)(sw + mat * 4096 + swz(ro + 8, pix >> 2) + (pix & 3)) =
                    make_float2(v2, v3);
            }
        }
    }
    __syncthreads();

    float* ob = out + (size_t)b * NPIX_B + pix0;
#pragma unroll
    for (int r = 0; r < 4; r++) {
        int idx = r * 256 + tid;
        int o = idx >> 4, p4 = idx & 15;
        int off = swz(o, p4);
        float4 v0 = *(float4*)(sw + off);
        float4 v1 = *(float4*)(sw + 4096 + off);
        float4 v2 = *(float4*)(sw + 2 * 4096 + off);
        float4 v3 = *(float4*)(sw + 3 * 4096 + off);
        float4 rr;
        rr.x = (v0.x + v1.x) + (v2.x + v3.x);
        rr.y = (v0.y + v1.y) + (v2.y + v3.y);
        rr.z = (v0.z + v1.z) + (v2.z + v3.z);
        rr.w = (v0.w + v1.w) + (v2.w + v3.w);
        *(float4*)(ob + (size_t)o * NPIX + p4 * 4) = rr;
    }
}

// ---------------------------------------------------------------------------
extern "C" void kernel_launch(void* const* d_in, const int* in_sizes, int n_in,
                              void* d_out, int out_size)
{
    const float* x     = (const float*)d_in[0];
    const float* fe_w  = (const float*)d_in[1];
    const float* fe_b  = (const float*)d_in[2];
    const float* s_w   = (const float*)d_in[3];
    const float* s_b   = (const float*)d_in[4];
    const float* e_w   = (const float*)d_in[5];
    const float* e_b   = (const float*)d_in[6];
    const float* g1_w  = (const float*)d_in[7];
    const float* g1_b  = (const float*)d_in[8];
    const float* bn1_g = (const float*)d_in[9];
    const float* bn1_b = (const float*)d_in[10];
    const float* ca1_w = (const float*)d_in[11];
    const float* ca1_b = (const float*)d_in[12];
    const float* ca2_w = (const float*)d_in[13];
    const float* ca2_b = (const float*)d_in[14];
    const float* g2_w  = (const float*)d_in[15];
    const float* g2_b  = (const float*)d_in[16];
    const float* bn2_g = (const float*)d_in[17];
    const float* bn2_b = (const float*)d_in[18];
    const float* g3_w  = (const float*)d_in[19];
    const float* g3_b  = (const float*)d_in[20];
    float* out = (float*)d_out;

    static bool attr_done = false;
    if (!attr_done) {
        cudaFuncSetAttribute(feat_kernel,
                             cudaFuncAttributeMaxDynamicSharedMemorySize,
                             12288 * sizeof(float));
        cudaFuncSetAttribute(out_kernel,
                             cudaFuncAttributeMaxDynamicSharedMemorySize,
                             20480 * sizeof(float));
        attr_done = true;
    }

    wquant_kernel<<<11, 256>>>(fe_w, s_w, e_w);
    feat_kernel<<<4096, 256, 12288 * sizeof(float)>>>(x, fe_b);
    gate_kernel<<<1, 256>>>(g1_w, g1_b, bn1_g, bn1_b, ca1_w, ca1_b,
                            ca2_w, ca2_b, g2_w, g2_b, bn2_g, bn2_b,
                            g3_w, g3_b);
    out_kernel<<<8192, 256, 20480 * sizeof(float)>>>(s_b, e_b, out);
}

// round 11
// speedup vs baseline: 1.8475x; 1.1083x over previous
#include <cuda_runtime.h>
#include <cuda_fp16.h>
#include <math.h>
#include <stdint.h>

// ---------------------------------------------------------------------------
// MoEImage via fp16 mma.sync m16n8k16 (fp32 accumulate).
//   wquant : round 11 64x64 weight matrices to fp16 ([o][k] layout)
//   feat   : F = gelu(x@W^T+b); d_feat stored [b][pix][c] fp16; fused gf sums
//   gate   : reduce gf partials (transposed, coalesced) -> MLP -> top2 -> d_dw
//   out    : 4-matrix fp16 GEMM; warp = (o-quarter, mat-pair), register
//            combine per pair, 2-buffer smem combine across pairs
// ---------------------------------------------------------------------------

#define NPIX   16384
#define NPIX_B (64 * 16384)

__device__ __align__(16) __half d_feat[32 * 64 * 16384];   // [b][pix][c], 64 MiB
__device__ float d_gf_part[64 * 4096];                     // [c][block]
__device__ float d_dw[32 * 8];
__device__ __align__(16) __half d_wq[11 * 4096];           // 0: fe, 1-2: shared, 3-10: experts

__device__ __forceinline__ float gelu_f(float v) {
    return 0.5f * v * (1.0f + erff(v * 0.70710678118654752440f));
}
// half tiles: rows of 64 halves = 128B = 8 segs of 16B; byte offset
__device__ __forceinline__ int swzb(int row, int seg) {
    return row * 128 + ((seg ^ (row & 7)) << 4);
}
// f32 tiles: rows of 64 floats = 16 segs of 16B; float offset
__device__ __forceinline__ int swz(int row, int seg) {
    return (row << 6) + ((seg ^ ((row ^ (row >> 3)) & 7)) << 2);
}
__device__ __forceinline__ void ldsm4(uint32_t a, uint32_t& r0, uint32_t& r1,
                                      uint32_t& r2, uint32_t& r3) {
    asm volatile("ldmatrix.sync.aligned.m8n8.x4.shared.b16 {%0,%1,%2,%3}, [%4];"
                 : "=r"(r0), "=r"(r1), "=r"(r2), "=r"(r3) : "r"(a));
}
__device__ __forceinline__ void mma16(float& c0, float& c1, float& c2, float& c3,
                                      uint32_t a0, uint32_t a1, uint32_t a2, uint32_t a3,
                                      uint32_t b0, uint32_t b1) {
    asm volatile("mma.sync.aligned.m16n8k16.row.col.f32.f16.f16.f32 "
                 "{%0,%1,%2,%3},{%4,%5,%6,%7},{%8,%9},{%0,%1,%2,%3};"
                 : "+f"(c0), "+f"(c1), "+f"(c2), "+f"(c3)
                 : "r"(a0), "r"(a1), "r"(a2), "r"(a3), "r"(b0), "r"(b1));
}
__device__ __forceinline__ uint32_t h2u(__half2 h) {
    return *reinterpret_cast<uint32_t*>(&h);
}

// --------------------------- weight quantize -------------------------------
__global__ __launch_bounds__(256) void wquant_kernel(
    const float* __restrict__ fe_w, const float* __restrict__ s_w,
    const float* __restrict__ e_w)
{
    const int m = blockIdx.x;   // 0..10
    const float* src = (m == 0) ? fe_w
                     : (m <= 2) ? s_w + (m - 1) * 4096
                                : e_w + (m - 3) * 4096;
    __half* dst = d_wq + m * 4096;
    for (int i = threadIdx.x; i < 4096; i += 256) dst[i] = __float2half_rn(src[i]);
}

// ------------------------------ Phase A ------------------------------------
// grid = 32 b * 128 tiles of 128 pix; block 256 = 8 warps.
// GEMM: m = pix (8 strips of 16), n = o (8 tiles), k = c (4 steps of 16).
__global__ void __launch_bounds__(256) feat_kernel(
    const float* __restrict__ x, const float* __restrict__ fe_b)
{
    extern __shared__ __align__(16) char smem[];
    // [0, 16KB)  sxT [128 pix][64 c] half swz; reused as sc [128 pix][64 o]
    // [16KB, 24KB) swt [64 o][64 k] half swz
    const uint32_t smem_sh = (uint32_t)__cvta_generic_to_shared(smem);
    __shared__ float sb[64];
    __shared__ float red[8 * 64];

    const int tid = threadIdx.x, w = tid >> 5, l = tid & 31;
    const int b = blockIdx.x >> 7, pix0 = (blockIdx.x & 127) << 7;

    // stage fe weights (fp16, pre-rounded)
#pragma unroll
    for (int r = 0; r < 2; r++) {
        int i4 = tid + r * 256;
        uint4 v = *(const uint4*)((const char*)d_wq + i4 * 16);
        *(uint4*)(smem + 16384 + swzb(i4 >> 3, i4 & 7)) = v;
    }
    if (tid < 64) sb[tid] = fe_b[tid];

    // stage x^T [pix][c] as fp16: warp w = channel octet, lane covers 4 pix
    {
        const float* xb = x + (size_t)b * NPIX_B + pix0;
        float4 v[8];
#pragma unroll
        for (int j = 0; j < 8; j++)
            v[j] = *(const float4*)(xb + (size_t)(8 * w + j) * NPIX + 4 * l);
#pragma unroll
        for (int p = 0; p < 4; p++) {
            uint4 u;
            u.x = h2u(__floats2half2_rn(((float*)&v[0])[p], ((float*)&v[1])[p]));
            u.y = h2u(__floats2half2_rn(((float*)&v[2])[p], ((float*)&v[3])[p]));
            u.z = h2u(__floats2half2_rn(((float*)&v[4])[p], ((float*)&v[5])[p]));
            u.w = h2u(__floats2half2_rn(((float*)&v[6])[p], ((float*)&v[7])[p]));
            *(uint4*)(smem + swzb(4 * l + p, w)) = u;
        }
    }
    __syncthreads();

    float acc[8][4];
    const int c0p = 2 * (l & 3);
#pragma unroll
    for (int nt = 0; nt < 8; nt++) {
        float b0v = sb[nt * 8 + c0p], b1v = sb[nt * 8 + c0p + 1];
        acc[nt][0] = b0v; acc[nt][1] = b1v;
        acc[nt][2] = b0v; acc[nt][3] = b1v;
    }

    const int tq = l >> 3, r8 = l & 7;
#pragma unroll
    for (int kk = 0; kk < 4; kk++) {
        const int aseg = 2 * kk + (tq >> 1);
        const int rsub = (tq & 1) * 8 + r8;
        uint32_t a0, a1, a2, a3;
        ldsm4(smem_sh + swzb(16 * w + rsub, aseg), a0, a1, a2, a3);
        uint32_t Bf[8][2];
#pragma unroll
        for (int g = 0; g < 4; g++) {
            uint32_t r0, r1, r2, r3;
            ldsm4(smem_sh + 16384 + swzb(16 * g + rsub, aseg), r0, r1, r2, r3);
            Bf[2 * g][0] = r0;     Bf[2 * g][1] = r2;
            Bf[2 * g + 1][0] = r1; Bf[2 * g + 1][1] = r3;
        }
#pragma unroll
        for (int nt = 0; nt < 8; nt++)
            mma16(acc[nt][0], acc[nt][1], acc[nt][2], acc[nt][3],
                  a0, a1, a2, a3, Bf[nt][0], Bf[nt][1]);
    }

    // gelu in fp32
#pragma unroll
    for (int nt = 0; nt < 8; nt++)
#pragma unroll
        for (int i = 0; i < 4; i++) acc[nt][i] = gelu_f(acc[nt][i]);

    // per-channel partial sums (fp32, before fp16 rounding)
#pragma unroll
    for (int nt = 0; nt < 8; nt++) {
        float p0 = acc[nt][0] + acc[nt][2];
        float p1 = acc[nt][1] + acc[nt][3];
#pragma unroll
        for (int mk = 4; mk <= 16; mk <<= 1) {
            p0 += __shfl_xor_sync(0xffffffffu, p0, mk);
            p1 += __shfl_xor_sync(0xffffffffu, p1, mk);
        }
        if (l < 4) {
            red[w * 64 + nt * 8 + 2 * l]     = p0;
            red[w * 64 + nt * 8 + 2 * l + 1] = p1;
        }
    }

    __syncthreads();   // sxT/swt reads done -> reuse sxT region as sc
    {
        const int pr = 16 * w + (l >> 2);
#pragma unroll
        for (int nt = 0; nt < 8; nt++) {
            __half2 lo = __floats2half2_rn(acc[nt][0], acc[nt][1]);
            __half2 hi = __floats2half2_rn(acc[nt][2], acc[nt][3]);
            *(__half2*)(smem + swzb(pr, nt) + c0p * 2) = lo;
            *(__half2*)(smem + swzb(pr + 8, nt) + c0p * 2) = hi;
        }
    }
    __syncthreads();

    // copy-out [pix][c] fp16
    char* fb = (char*)(d_feat + ((size_t)b * NPIX + pix0) * 64);
#pragma unroll
    for (int r = 0; r < 4; r++) {
        int i4 = tid + r * 256;
        uint4 v = *(uint4*)(smem + swzb(i4 >> 3, i4 & 7));
        *(uint4*)(fb + i4 * 16) = v;
    }
    if (tid < 64) {
        float s = 0.f;
#pragma unroll
        for (int ww = 0; ww < 8; ww++) s += red[ww * 64 + tid];
        d_gf_part[tid * 4096 + blockIdx.x] = s;
    }
}

// ------------------------------ Phase C ------------------------------------
__global__ __launch_bounds__(256) void gate_kernel(
    const float* __restrict__ g1_w, const float* __restrict__ g1_b,
    const float* __restrict__ bn1_g, const float* __restrict__ bn1_b,
    const float* __restrict__ ca1_w, const float* __restrict__ ca1_b,
    const float* __restrict__ ca2_w, const float* __restrict__ ca2_b,
    const float* __restrict__ g2_w, const float* __restrict__ g2_b,
    const float* __restrict__ bn2_g, const float* __restrict__ bn2_b,
    const float* __restrict__ g3_w, const float* __restrict__ g3_b)
{
    __shared__ float sgf[32 * 64];
    __shared__ float sh1[32 * 128];
    __shared__ float sm[32 * 8];
    __shared__ float shh[32 * 64];
    __shared__ float ssc[32 * 8];
    const int tid = threadIdx.x;
    const float rs = rsqrtf(1.0f + 1e-5f);

    for (int i = tid; i < 2048; i += 256) {
        int bb = i >> 6, c = i & 63;
        const float4* pp = (const float4*)(d_gf_part + c * 4096 + bb * 128);
        float s = 0.f;
#pragma unroll 8
        for (int j = 0; j < 32; j++) {
            float4 v = pp[j];
            s += (v.x + v.y) + (v.z + v.w);
        }
        sgf[i] = s * (1.0f / 16384.0f);
    }
    __syncthreads();

    for (int i = tid; i < 32 * 128; i += 256) {
        int b = i >> 7, j = i & 127;
        float a = g1_b[j];
        const float* gr = sgf + b * 64;
        const float* wr = g1_w + j * 64;
#pragma unroll 8
        for (int c = 0; c < 64; c++) a = fmaf(gr[c], wr[c], a);
        a = a * (bn1_g[j] * rs) + bn1_b[j];
        sh1[i] = gelu_f(a);
    }
    __syncthreads();

    {
        int b = tid >> 3, k = tid & 7;
        float a = ca1_b[k];
        const float* hr = sh1 + b * 128;
        const float* wr = ca1_w + k * 128;
#pragma unroll 8
        for (int j = 0; j < 128; j++) a = fmaf(hr[j], wr[j], a);
        sm[tid] = gelu_f(a);
    }
    __syncthreads();

    for (int i = tid; i < 32 * 128; i += 256) {
        int b = i >> 7, j = i & 127;
        float a = ca2_b[j];
        const float* mr = sm + b * 8;
        const float* wr = ca2_w + j * 8;
#pragma unroll
        for (int k = 0; k < 8; k++) a = fmaf(mr[k], wr[k], a);
        sh1[i] *= 1.0f / (1.0f + expf(-2.0f * a));
    }
    __syncthreads();

    for (int i = tid; i < 32 * 64; i += 256) {
        int b = i >> 6, o = i & 63;
        float a = g2_b[o];
        const float* hr = sh1 + b * 128;
        const float* wr = g2_w + o * 128;
#pragma unroll 8
        for (int j = 0; j < 128; j++) a = fmaf(hr[j], wr[j], a);
        a = a * (bn2_g[o] * rs) + bn2_b[o];
        shh[i] = gelu_f(a);
    }
    __syncthreads();

    {
        int b = tid >> 3, e = tid & 7;
        float a = g3_b[e];
        const float* hr = shh + b * 64;
        const float* wr = g3_w + e * 64;
#pragma unroll 8
        for (int c = 0; c < 64; c++) a = fmaf(hr[c], wr[c], a);
        ssc[tid] = a;
    }
    __syncthreads();

    if (tid < 32) {
        const float* sc = ssc + tid * 8;
        int i1 = 0; float v1 = sc[0];
#pragma unroll
        for (int e = 1; e < 8; e++) if (sc[e] > v1) { v1 = sc[e]; i1 = e; }
        int i2 = -1; float v2 = -3.4e38f;
#pragma unroll
        for (int e = 0; e < 8; e++) if (e != i1 && sc[e] > v2) { v2 = sc[e]; i2 = e; }
        float w1 = 1.0f / (1.0f + expf((v2 - v1) * 0.5f));
        float* dw = d_dw + tid * 8;
#pragma unroll
        for (int e = 0; e < 8; e++) dw[e] = 0.0f;
        dw[i1] = w1;
        dw[i2] = 1.0f - w1;
    }
}

// ------------------------------ Phase D ------------------------------------
// grid = 32 b * 256 tiles of 64 pix; block 256 = 8 warps.
// warp: q = w&3 -> o rows [16q,16q+16); g = w>>2 -> mats {2g, 2g+1}.
// A = weights [o][k] fp16, B = features [pix][k] fp16; B frags shared by pair.
__global__ void __launch_bounds__(256, 2) out_kernel(
    const float* __restrict__ s_b, const float* __restrict__ e_b,
    float* __restrict__ out)
{
    extern __shared__ __align__(16) char smem[];
    // [0, 8KB)     sfB [64 pix][64 k] half swz
    // [8KB, 40KB)  sw4 [4 mat][64 o][64 k] half swz; reused: buf[2][64][64] f32
    const uint32_t smem_sh = (uint32_t)__cvta_generic_to_shared(smem);
    __shared__ float Bv[256];
    __shared__ float cws[4];
    __shared__ int msel[4];

    const int tid = threadIdx.x, w = tid >> 5, l = tid & 31;
    const int b = blockIdx.x >> 8, pix0 = (blockIdx.x & 255) << 6;

    if (tid == 0) {
        int s0 = -1, s1 = -1; float w0 = 0.f, w1 = 0.f;
        const float* dw = d_dw + b * 8;
#pragma unroll
        for (int e = 0; e < 8; e++) {
            float v = dw[e];
            if (v != 0.0f) { if (s0 < 0) { s0 = e; w0 = v; } else { s1 = e; w1 = v; } }
        }
        msel[0] = 1; msel[1] = 2; msel[2] = 3 + s0; msel[3] = 3 + s1;
        cws[0] = 0.5f; cws[1] = 0.5f; cws[2] = w0; cws[3] = w1;
    }
    __syncthreads();

    // stage 4 weight matrices (fp16, swizzled): 2048 uint4
#pragma unroll
    for (int r = 0; r < 8; r++) {
        int idx = tid + r * 256;
        int m = idx >> 9, i4 = idx & 511;
        uint4 v = *(const uint4*)((const char*)d_wq + msel[m] * 8192 + i4 * 16);
        *(uint4*)(smem + 8192 + m * 8192 + swzb(i4 >> 3, i4 & 7)) = v;
    }
    // stage features [pix][k] (contiguous fp16 rows): 512 uint4
    {
        const char* fb = (const char*)(d_feat + ((size_t)b * NPIX + pix0) * 64);
#pragma unroll
        for (int r = 0; r < 2; r++) {
            int i4 = tid + r * 256;
            uint4 v = *(const uint4*)(fb + i4 * 16);
            *(uint4*)(smem + swzb(i4 >> 3, i4 & 7)) = v;
        }
    }
    if (tid < 64) {
        Bv[tid]       = s_b[tid];
        Bv[64 + tid]  = s_b[64 + tid];
        Bv[128 + tid] = e_b[(msel[2] - 3) * 64 + tid];
        Bv[192 + tid] = e_b[(msel[3] - 3) * 64 + tid];
    }
    __syncthreads();

    const int q = w & 3, g = w >> 2;
    const int ma = 2 * g, mb = 2 * g + 1;
    const uint32_t swa = smem_sh + 8192 + ma * 8192;
    const uint32_t swb = smem_sh + 8192 + mb * 8192;

    const int ro = 16 * q + (l >> 2), c0p = 2 * (l & 3);
    float accA[8][4], accB[8][4];
#pragma unroll
    for (int nt = 0; nt < 8; nt++) {
        float a0v = Bv[ma * 64 + ro], a1v = Bv[ma * 64 + ro + 8];
        float b0v = Bv[mb * 64 + ro], b1v = Bv[mb * 64 + ro + 8];
        accA[nt][0] = a0v; accA[nt][1] = a0v; accA[nt][2] = a1v; accA[nt][3] = a1v;
        accB[nt][0] = b0v; accB[nt][1] = b0v; accB[nt][2] = b1v; accB[nt][3] = b1v;
    }

    const int tq = l >> 3, r8 = l & 7;
#pragma unroll
    for (int kk = 0; kk < 4; kk++) {
        const int aseg = 2 * kk + (tq >> 1);
        const int rsub = (tq & 1) * 8 + r8;
        uint32_t Bf[8][2];
#pragma unroll
        for (int g2 = 0; g2 < 4; g2++) {
            uint32_t r0, r1, r2, r3;
            ldsm4(smem_sh + swzb(16 * g2 + rsub, aseg), r0, r1, r2, r3);
            Bf[2 * g2][0] = r0;     Bf[2 * g2][1] = r2;
            Bf[2 * g2 + 1][0] = r1; Bf[2 * g2 + 1][1] = r3;
        }
        uint32_t a0, a1, a2, a3;
        ldsm4(swa + swzb(16 * q + rsub, aseg), a0, a1, a2, a3);
#pragma unroll
        for (int nt = 0; nt < 8; nt++)
            mma16(accA[nt][0], accA[nt][1], accA[nt][2], accA[nt][3],
                  a0, a1, a2, a3, Bf[nt][0], Bf[nt][1]);
        ldsm4(swb + swzb(16 * q + rsub, aseg), a0, a1, a2, a3);
#pragma unroll
        for (int nt = 0; nt < 8; nt++)
            mma16(accB[nt][0], accB[nt][1], accB[nt][2], accB[nt][3],
                  a0, a1, a2, a3, Bf[nt][0], Bf[nt][1]);
    }

    const float ca = cws[ma], cb = cws[mb];
    __syncthreads();   // weights dead -> reuse as 2 combine buffers [g][o][pix] f32
    {
        float* buf = (float*)(smem + 8192) + g * 4096;
#pragma unroll
        for (int nt = 0; nt < 8; nt++) {
            int pix = nt * 8 + c0p;
            float v0 = ca * gelu_f(accA[nt][0]) + cb * gelu_f(accB[nt][0]);
            float v1 = ca * gelu_f(accA[nt][1]) + cb * gelu_f(accB[nt][1]);
            float v2 = ca * gelu_f(accA[nt][2]) + cb * gelu_f(accB[nt][2]);
            float v3 = ca * gelu_f(accA[nt][3]) + cb * gelu_f(accB[nt][3]);
            *(float2*)(buf + swz(ro, pix >> 2) + (pix & 3))     = make_float2(v0, v1);
            *(float2*)(buf + swz(ro + 8, pix >> 2) + (pix & 3)) = make_float2(v2, v3);
        }
    }
    __syncthreads();

    float* ob = out + (size_t)b * NPIX_B + pix0;
    const float* b0p = (const float*)(smem + 8192);
    const float* b1p = b0p + 4096;
#pragma unroll
    for (int r = 0; r < 4; r++) {
        int i4 = tid + r * 256;
        int o = i4 >> 4, seg = i4 & 15;
        int off = swz(o, seg);
        float4 va = *(const float4*)(b0p + off);
        float4 vb = *(const float4*)(b1p + off);
        float4 rr;
        rr.x = va.x + vb.x; rr.y = va.y + vb.y;
        rr.z = va.z + vb.z; rr.w = va.w + vb.w;
        *(float4*)(ob + (size_t)o * NPIX + seg * 4) = rr;
    }
}

// ---------------------------------------------------------------------------
extern "C" void kernel_launch(void* const* d_in, const int* in_sizes, int n_in,
                              void* d_out, int out_size)
{
    const float* x     = (const float*)d_in[0];
    const float* fe_w  = (const float*)d_in[1];
    const float* fe_b  = (const float*)d_in[2];
    const float* s_w   = (const float*)d_in[3];
    const float* s_b   = (const float*)d_in[4];
    const float* e_w   = (const float*)d_in[5];
    const float* e_b   = (const float*)d_in[6];
    const float* g1_w  = (const float*)d_in[7];
    const float* g1_b  = (const float*)d_in[8];
    const float* bn1_g = (const float*)d_in[9];
    const float* bn1_b = (const float*)d_in[10];
    const float* ca1_w = (const float*)d_in[11];
    const float* ca1_b = (const float*)d_in[12];
    const float* ca2_w = (const float*)d_in[13];
    const float* ca2_b = (const float*)d_in[14];
    const float* g2_w  = (const float*)d_in[15];
    const float* g2_b  = (const float*)d_in[16];
    const float* bn2_g = (const float*)d_in[17];
    const float* bn2_b = (const float*)d_in[18];
    const float* g3_w  = (const float*)d_in[19];
    const float* g3_b  = (const float*)d_in[20];
    float* out = (float*)d_out;

    wquant_kernel<<<11, 256>>>(fe_w, s_w, e_w);
    feat_kernel<<<4096, 256, 24576>>>(x, fe_b);
    gate_kernel<<<1, 256>>>(g1_w, g1_b, bn1_g, bn1_b, ca1_w, ca1_b,
                            ca2_w, ca2_b, g2_w, g2_b, bn2_g, bn2_b,
                            g3_w, g3_b);
    out_kernel<<<8192, 256, 40960>>>(s_b, e_b, out);
}